// round 1
// baseline (speedup 1.0000x reference)
#include <cuda_runtime.h>
#include <math_constants.h>

#define BATCH 4
#define SEQ   2048
#define DM    1024
#define NH    16
#define HD    64
#define MTOT  (BATCH*SEQ)   // 8192

// Scratch (device globals: allocation-free rule)
__device__ float g_Q[BATCH*NH*SEQ*HD];  // [b,h,s,hd]
__device__ float g_K[BATCH*NH*SEQ*HD];
__device__ float g_V[BATCH*NH*SEQ*HD];
__device__ float g_Y[MTOT*DM];          // [b,s,D] attention output

// ---------------------------------------------------------------------------
// GEMM + bias: C = A[M,1024] @ W[1024,1024] + bias
// MODE 0: write head-split layout [b,h,s,hd]; MODE 1: row-major [m,n]
// 64x64 block tile, BK=16, 256 threads, 4x4 per thread.
// ---------------------------------------------------------------------------
template<int MODE>
__global__ __launch_bounds__(256)
void gemm_bias(const float* __restrict__ A,
               const float* __restrict__ W,
               const float* __restrict__ bias,
               float* __restrict__ C) {
    __shared__ float As[64][17];   // [m][k], pad 17 (odd) -> conflict-light
    __shared__ float Bs[16][68];   // [k][n], pad 68 keeps float4 alignment

    const int tid = threadIdx.x;
    const int tx  = tid & 15;      // n-tile
    const int ty  = tid >> 4;      // m-tile
    const int bm  = blockIdx.y << 6;
    const int bn  = blockIdx.x << 6;

    float acc[4][4] = {};

    const int a_m = tid >> 2;            // 0..63
    const int a_k = (tid & 3) << 2;      // 0,4,8,12
    const int b_k = tid >> 4;            // 0..15
    const int b_n = (tid & 15) << 2;     // 0..60

    const float* Aptr = A + (size_t)(bm + a_m) * DM + a_k;
    const float* Wptr = W + (size_t)b_k * DM + bn + b_n;

    for (int kt = 0; kt < DM; kt += 16) {
        float4 av = *reinterpret_cast<const float4*>(Aptr + kt);
        float4 bv = *reinterpret_cast<const float4*>(Wptr + (size_t)kt * DM);
        As[a_m][a_k+0] = av.x; As[a_m][a_k+1] = av.y;
        As[a_m][a_k+2] = av.z; As[a_m][a_k+3] = av.w;
        *reinterpret_cast<float4*>(&Bs[b_k][b_n]) = bv;
        __syncthreads();

        #pragma unroll
        for (int d = 0; d < 16; d++) {
            float a0 = As[ty*4+0][d];
            float a1 = As[ty*4+1][d];
            float a2 = As[ty*4+2][d];
            float a3 = As[ty*4+3][d];
            float4 b = *reinterpret_cast<const float4*>(&Bs[d][tx*4]);
            acc[0][0] += a0*b.x; acc[0][1] += a0*b.y; acc[0][2] += a0*b.z; acc[0][3] += a0*b.w;
            acc[1][0] += a1*b.x; acc[1][1] += a1*b.y; acc[1][2] += a1*b.z; acc[1][3] += a1*b.w;
            acc[2][0] += a2*b.x; acc[2][1] += a2*b.y; acc[2][2] += a2*b.z; acc[2][3] += a2*b.w;
            acc[3][0] += a3*b.x; acc[3][1] += a3*b.y; acc[3][2] += a3*b.z; acc[3][3] += a3*b.w;
        }
        __syncthreads();
    }

    float4 bb = *reinterpret_cast<const float4*>(&bias[bn + tx*4]);
    #pragma unroll
    for (int i = 0; i < 4; i++) {
        int m = bm + ty*4 + i;
        float4 ov;
        ov.x = acc[i][0] + bb.x;
        ov.y = acc[i][1] + bb.y;
        ov.z = acc[i][2] + bb.z;
        ov.w = acc[i][3] + bb.w;
        if (MODE == 0) {
            // n = bn + tx*4 + j ; bn is a multiple of 64 so head = bn>>6 for all j
            int b = m >> 11, s = m & (SEQ-1);
            int h = bn >> 6, dd = tx*4;
            *reinterpret_cast<float4*>(&C[(((size_t)(b*NH + h)*SEQ) + s)*HD + dd]) = ov;
        } else {
            *reinterpret_cast<float4*>(&C[(size_t)m*DM + bn + tx*4]) = ov;
        }
    }
}

// ---------------------------------------------------------------------------
// Flash attention: per (b,h), 64-query blocks iterate over 64-key tiles.
// Q,K,V in [b,h,s,hd]; output Y in [b,s,D].
// 256 threads; S-tile 64x64 with 4x4 per thread; P staged via smem.
// ---------------------------------------------------------------------------
#define QS_LD 65
#define KS_LD 65
#define VS_LD 68
#define PS_LD 65
#define SMEM_FLOATS (64*QS_LD + 64*KS_LD + 64*VS_LD + 64*PS_LD)

__global__ __launch_bounds__(256)
void attn_kernel(const float* __restrict__ Q,
                 const float* __restrict__ K,
                 const float* __restrict__ V,
                 float* __restrict__ Y) {
    extern __shared__ float sm[];
    float* Qs = sm;                                  // [64][65]
    float* Ks = sm + 64*QS_LD;                       // [64][65]
    float* Vs = sm + 64*(QS_LD + KS_LD);             // [64][68]
    float* Ps = sm + 64*(QS_LD + KS_LD + VS_LD);     // [64][65]

    const int tid = threadIdx.x;
    const int tx = tid & 15;
    const int ty = tid >> 4;
    const int qb = blockIdx.x << 6;
    const int bh = blockIdx.y;              // b*NH + h

    const float* Qp = Q + ((size_t)bh * SEQ + qb) * HD;
    const float* Kp = K + (size_t)bh * SEQ * HD;
    const float* Vp = V + (size_t)bh * SEQ * HD;

    // Load Q tile, folding in softmax scale 1/sqrt(64) = 0.125
    #pragma unroll
    for (int it = 0; it < 4; it++) {
        int idx = it * 256 + tid;
        int r = idx >> 4, c = (idx & 15) << 2;
        float4 v = *reinterpret_cast<const float4*>(Qp + (size_t)r * HD + c);
        Qs[r*QS_LD + c+0] = v.x * 0.125f;
        Qs[r*QS_LD + c+1] = v.y * 0.125f;
        Qs[r*QS_LD + c+2] = v.z * 0.125f;
        Qs[r*QS_LD + c+3] = v.w * 0.125f;
    }

    float m_i[4], l_i[4], o[4][4];
    #pragma unroll
    for (int i = 0; i < 4; i++) {
        m_i[i] = -CUDART_INF_F;
        l_i[i] = 0.f;
        #pragma unroll
        for (int j = 0; j < 4; j++) o[i][j] = 0.f;
    }

    for (int kb = 0; kb < SEQ; kb += 64) {
        __syncthreads();   // protect Ks/Vs/Ps reuse from previous iteration
        #pragma unroll
        for (int it = 0; it < 4; it++) {
            int idx = it * 256 + tid;
            int r = idx >> 4, c = (idx & 15) << 2;
            float4 kv = *reinterpret_cast<const float4*>(Kp + (size_t)(kb + r) * HD + c);
            Ks[r*KS_LD + c+0] = kv.x; Ks[r*KS_LD + c+1] = kv.y;
            Ks[r*KS_LD + c+2] = kv.z; Ks[r*KS_LD + c+3] = kv.w;
            float4 vv = *reinterpret_cast<const float4*>(Vp + (size_t)(kb + r) * HD + c);
            *reinterpret_cast<float4*>(&Vs[r*VS_LD + c]) = vv;
        }
        __syncthreads();

        // S = (Q*scale) @ K^T for this tile
        float s_acc[4][4] = {};
        #pragma unroll 8
        for (int d = 0; d < 64; d++) {
            float qv[4], kv[4];
            #pragma unroll
            for (int i = 0; i < 4; i++) qv[i] = Qs[(ty*4+i)*QS_LD + d];
            #pragma unroll
            for (int j = 0; j < 4; j++) kv[j] = Ks[(tx*4+j)*KS_LD + d];
            #pragma unroll
            for (int i = 0; i < 4; i++)
                #pragma unroll
                for (int j = 0; j < 4; j++)
                    s_acc[i][j] += qv[i] * kv[j];
        }

        // Online softmax (row groups of 16 lanes share a query row set)
        #pragma unroll
        for (int i = 0; i < 4; i++) {
            float mx = fmaxf(fmaxf(s_acc[i][0], s_acc[i][1]),
                             fmaxf(s_acc[i][2], s_acc[i][3]));
            #pragma unroll
            for (int off = 8; off > 0; off >>= 1)
                mx = fmaxf(mx, __shfl_xor_sync(0xffffffffu, mx, off));
            float mnew = fmaxf(m_i[i], mx);
            float alpha = __expf(m_i[i] - mnew);
            float rs = 0.f;
            #pragma unroll
            for (int j = 0; j < 4; j++) {
                float p = __expf(s_acc[i][j] - mnew);
                Ps[(ty*4+i)*PS_LD + tx*4 + j] = p;
                rs += p;
            }
            #pragma unroll
            for (int off = 8; off > 0; off >>= 1)
                rs += __shfl_xor_sync(0xffffffffu, rs, off);
            l_i[i] = l_i[i] * alpha + rs;
            m_i[i] = mnew;
            o[i][0] *= alpha; o[i][1] *= alpha; o[i][2] *= alpha; o[i][3] *= alpha;
        }
        __syncthreads();

        // O += P @ V
        #pragma unroll 8
        for (int k = 0; k < 64; k++) {
            float4 v4 = *reinterpret_cast<const float4*>(&Vs[k*VS_LD + tx*4]);
            #pragma unroll
            for (int i = 0; i < 4; i++) {
                float p = Ps[(ty*4+i)*PS_LD + k];
                o[i][0] += p * v4.x;
                o[i][1] += p * v4.y;
                o[i][2] += p * v4.z;
                o[i][3] += p * v4.w;
            }
        }
    }

    // Write normalized output to [b,s,D]
    const int b = bh >> 4, h = bh & (NH-1);
    #pragma unroll
    for (int i = 0; i < 4; i++) {
        float inv = 1.0f / l_i[i];
        size_t row = (size_t)b * SEQ + qb + ty*4 + i;
        float4 ov;
        ov.x = o[i][0]*inv; ov.y = o[i][1]*inv;
        ov.z = o[i][2]*inv; ov.w = o[i][3]*inv;
        *reinterpret_cast<float4*>(&Y[row*DM + h*HD + tx*4]) = ov;
    }
}

// ---------------------------------------------------------------------------
extern "C" void kernel_launch(void* const* d_in, const int* in_sizes, int n_in,
                              void* d_out, int out_size) {
    const float* x  = (const float*)d_in[0];
    const float* Wq = (const float*)d_in[1];
    const float* bq = (const float*)d_in[2];
    const float* Wk = (const float*)d_in[3];
    const float* bk = (const float*)d_in[4];
    const float* Wv = (const float*)d_in[5];
    const float* bv = (const float*)d_in[6];
    const float* Wo = (const float*)d_in[7];
    const float* bo = (const float*)d_in[8];
    float* out = (float*)d_out;

    float *qp, *kp, *vp, *yp;
    cudaGetSymbolAddress((void**)&qp, g_Q);
    cudaGetSymbolAddress((void**)&kp, g_K);
    cudaGetSymbolAddress((void**)&vp, g_V);
    cudaGetSymbolAddress((void**)&yp, g_Y);

    dim3 gg(DM/64, MTOT/64);   // (16, 128)
    gemm_bias<0><<<gg, 256>>>(x, Wq, bq, qp);
    gemm_bias<0><<<gg, 256>>>(x, Wk, bk, kp);
    gemm_bias<0><<<gg, 256>>>(x, Wv, bv, vp);

    size_t smem = SMEM_FLOATS * sizeof(float);   // ~67 KB
    cudaFuncSetAttribute(attn_kernel,
                         cudaFuncAttributeMaxDynamicSharedMemorySize, (int)smem);
    attn_kernel<<<dim3(SEQ/64, BATCH*NH), 256, smem>>>(qp, kp, vp, yp);

    gemm_bias<1><<<gg, 256>>>(yp, Wo, bo, out);
}

// round 2
// speedup vs baseline: 1.0006x; 1.0006x over previous
#include <cuda_runtime.h>
#include <math_constants.h>

#define BATCH 4
#define SEQ   2048
#define DM    1024
#define NH    16
#define HD    64
#define MTOT  (BATCH*SEQ)   // 8192

// Scratch (device globals: allocation-free rule)
__device__ float g_Q[BATCH*NH*SEQ*HD];  // [b,h,s,hd]
__device__ float g_K[BATCH*NH*SEQ*HD];
__device__ float g_V[BATCH*NH*SEQ*HD];
__device__ float g_Y[MTOT*DM];          // [b,s,D] attention output

// ---------------------------------------------------------------------------
// GEMM + bias: C = A[M,1024] @ W[1024,1024] + bias
// MODE 0: write head-split layout [b,h,s,hd]; MODE 1: row-major [m,n]
// 64x64 block tile, BK=16, 256 threads, 4x4 per thread.
// ---------------------------------------------------------------------------
template<int MODE>
__global__ __launch_bounds__(256)
void gemm_bias(const float* __restrict__ A,
               const float* __restrict__ W,
               const float* __restrict__ bias,
               float* __restrict__ C) {
    __shared__ float As[64][17];   // [m][k], pad 17 (odd) -> conflict-light
    __shared__ float Bs[16][68];   // [k][n], pad 68 keeps float4 alignment

    const int tid = threadIdx.x;
    const int tx  = tid & 15;      // n-tile
    const int ty  = tid >> 4;      // m-tile
    const int bm  = blockIdx.y << 6;
    const int bn  = blockIdx.x << 6;

    float acc[4][4] = {};

    const int a_m = tid >> 2;            // 0..63
    const int a_k = (tid & 3) << 2;      // 0,4,8,12
    const int b_k = tid >> 4;            // 0..15
    const int b_n = (tid & 15) << 2;     // 0..60

    const float* Aptr = A + (size_t)(bm + a_m) * DM + a_k;
    const float* Wptr = W + (size_t)b_k * DM + bn + b_n;

    for (int kt = 0; kt < DM; kt += 16) {
        float4 av = *reinterpret_cast<const float4*>(Aptr + kt);
        float4 bv = *reinterpret_cast<const float4*>(Wptr + (size_t)kt * DM);
        As[a_m][a_k+0] = av.x; As[a_m][a_k+1] = av.y;
        As[a_m][a_k+2] = av.z; As[a_m][a_k+3] = av.w;
        *reinterpret_cast<float4*>(&Bs[b_k][b_n]) = bv;
        __syncthreads();

        #pragma unroll
        for (int d = 0; d < 16; d++) {
            float a0 = As[ty*4+0][d];
            float a1 = As[ty*4+1][d];
            float a2 = As[ty*4+2][d];
            float a3 = As[ty*4+3][d];
            float4 b = *reinterpret_cast<const float4*>(&Bs[d][tx*4]);
            acc[0][0] += a0*b.x; acc[0][1] += a0*b.y; acc[0][2] += a0*b.z; acc[0][3] += a0*b.w;
            acc[1][0] += a1*b.x; acc[1][1] += a1*b.y; acc[1][2] += a1*b.z; acc[1][3] += a1*b.w;
            acc[2][0] += a2*b.x; acc[2][1] += a2*b.y; acc[2][2] += a2*b.z; acc[2][3] += a2*b.w;
            acc[3][0] += a3*b.x; acc[3][1] += a3*b.y; acc[3][2] += a3*b.z; acc[3][3] += a3*b.w;
        }
        __syncthreads();
    }

    float4 bb = *reinterpret_cast<const float4*>(&bias[bn + tx*4]);
    #pragma unroll
    for (int i = 0; i < 4; i++) {
        int m = bm + ty*4 + i;
        float4 ov;
        ov.x = acc[i][0] + bb.x;
        ov.y = acc[i][1] + bb.y;
        ov.z = acc[i][2] + bb.z;
        ov.w = acc[i][3] + bb.w;
        if (MODE == 0) {
            // n = bn + tx*4 + j ; bn is a multiple of 64 so head = bn>>6 for all j
            int b = m >> 11, s = m & (SEQ-1);
            int h = bn >> 6, dd = tx*4;
            *reinterpret_cast<float4*>(&C[(((size_t)(b*NH + h)*SEQ) + s)*HD + dd]) = ov;
        } else {
            *reinterpret_cast<float4*>(&C[(size_t)m*DM + bn + tx*4]) = ov;
        }
    }
}

// ---------------------------------------------------------------------------
// Flash attention: per (b,h), 64-query blocks iterate over 64-key tiles.
// Q,K,V in [b,h,s,hd]; output Y in [b,s,D].
// 256 threads; S-tile 64x64 with 4x4 per thread; P staged via smem.
// ---------------------------------------------------------------------------
#define QS_LD 65
#define KS_LD 65
#define VS_LD 68
#define PS_LD 65
#define SMEM_FLOATS (64*QS_LD + 64*KS_LD + 64*VS_LD + 64*PS_LD)

__global__ __launch_bounds__(256)
void attn_kernel(const float* __restrict__ Q,
                 const float* __restrict__ K,
                 const float* __restrict__ V,
                 float* __restrict__ Y) {
    extern __shared__ float sm[];
    float* Qs = sm;                                  // [64][65]
    float* Ks = sm + 64*QS_LD;                       // [64][65]
    float* Vs = sm + 64*(QS_LD + KS_LD);             // [64][68]
    float* Ps = sm + 64*(QS_LD + KS_LD + VS_LD);     // [64][65]

    const int tid = threadIdx.x;
    const int tx = tid & 15;
    const int ty = tid >> 4;
    const int qb = blockIdx.x << 6;
    const int bh = blockIdx.y;              // b*NH + h

    const float* Qp = Q + ((size_t)bh * SEQ + qb) * HD;
    const float* Kp = K + (size_t)bh * SEQ * HD;
    const float* Vp = V + (size_t)bh * SEQ * HD;

    // Load Q tile, folding in softmax scale 1/sqrt(64) = 0.125
    #pragma unroll
    for (int it = 0; it < 4; it++) {
        int idx = it * 256 + tid;
        int r = idx >> 4, c = (idx & 15) << 2;
        float4 v = *reinterpret_cast<const float4*>(Qp + (size_t)r * HD + c);
        Qs[r*QS_LD + c+0] = v.x * 0.125f;
        Qs[r*QS_LD + c+1] = v.y * 0.125f;
        Qs[r*QS_LD + c+2] = v.z * 0.125f;
        Qs[r*QS_LD + c+3] = v.w * 0.125f;
    }

    float m_i[4], l_i[4], o[4][4];
    #pragma unroll
    for (int i = 0; i < 4; i++) {
        m_i[i] = -CUDART_INF_F;
        l_i[i] = 0.f;
        #pragma unroll
        for (int j = 0; j < 4; j++) o[i][j] = 0.f;
    }

    for (int kb = 0; kb < SEQ; kb += 64) {
        __syncthreads();   // protect Ks/Vs/Ps reuse from previous iteration
        #pragma unroll
        for (int it = 0; it < 4; it++) {
            int idx = it * 256 + tid;
            int r = idx >> 4, c = (idx & 15) << 2;
            float4 kv = *reinterpret_cast<const float4*>(Kp + (size_t)(kb + r) * HD + c);
            Ks[r*KS_LD + c+0] = kv.x; Ks[r*KS_LD + c+1] = kv.y;
            Ks[r*KS_LD + c+2] = kv.z; Ks[r*KS_LD + c+3] = kv.w;
            float4 vv = *reinterpret_cast<const float4*>(Vp + (size_t)(kb + r) * HD + c);
            *reinterpret_cast<float4*>(&Vs[r*VS_LD + c]) = vv;
        }
        __syncthreads();

        // S = (Q*scale) @ K^T for this tile
        float s_acc[4][4] = {};
        #pragma unroll 8
        for (int d = 0; d < 64; d++) {
            float qv[4], kv[4];
            #pragma unroll
            for (int i = 0; i < 4; i++) qv[i] = Qs[(ty*4+i)*QS_LD + d];
            #pragma unroll
            for (int j = 0; j < 4; j++) kv[j] = Ks[(tx*4+j)*KS_LD + d];
            #pragma unroll
            for (int i = 0; i < 4; i++)
                #pragma unroll
                for (int j = 0; j < 4; j++)
                    s_acc[i][j] += qv[i] * kv[j];
        }

        // Online softmax (row groups of 16 lanes share a query row set)
        #pragma unroll
        for (int i = 0; i < 4; i++) {
            float mx = fmaxf(fmaxf(s_acc[i][0], s_acc[i][1]),
                             fmaxf(s_acc[i][2], s_acc[i][3]));
            #pragma unroll
            for (int off = 8; off > 0; off >>= 1)
                mx = fmaxf(mx, __shfl_xor_sync(0xffffffffu, mx, off));
            float mnew = fmaxf(m_i[i], mx);
            float alpha = __expf(m_i[i] - mnew);
            float rs = 0.f;
            #pragma unroll
            for (int j = 0; j < 4; j++) {
                float p = __expf(s_acc[i][j] - mnew);
                Ps[(ty*4+i)*PS_LD + tx*4 + j] = p;
                rs += p;
            }
            #pragma unroll
            for (int off = 8; off > 0; off >>= 1)
                rs += __shfl_xor_sync(0xffffffffu, rs, off);
            l_i[i] = l_i[i] * alpha + rs;
            m_i[i] = mnew;
            o[i][0] *= alpha; o[i][1] *= alpha; o[i][2] *= alpha; o[i][3] *= alpha;
        }
        __syncthreads();

        // O += P @ V
        #pragma unroll 8
        for (int k = 0; k < 64; k++) {
            float4 v4 = *reinterpret_cast<const float4*>(&Vs[k*VS_LD + tx*4]);
            #pragma unroll
            for (int i = 0; i < 4; i++) {
                float p = Ps[(ty*4+i)*PS_LD + k];
                o[i][0] += p * v4.x;
                o[i][1] += p * v4.y;
                o[i][2] += p * v4.z;
                o[i][3] += p * v4.w;
            }
        }
    }

    // Write normalized output to [b,s,D]
    const int b = bh >> 4, h = bh & (NH-1);
    #pragma unroll
    for (int i = 0; i < 4; i++) {
        float inv = 1.0f / l_i[i];
        size_t row = (size_t)b * SEQ + qb + ty*4 + i;
        float4 ov;
        ov.x = o[i][0]*inv; ov.y = o[i][1]*inv;
        ov.z = o[i][2]*inv; ov.w = o[i][3]*inv;
        *reinterpret_cast<float4*>(&Y[row*DM + h*HD + tx*4]) = ov;
    }
}

// ---------------------------------------------------------------------------
extern "C" void kernel_launch(void* const* d_in, const int* in_sizes, int n_in,
                              void* d_out, int out_size) {
    const float* x  = (const float*)d_in[0];
    const float* Wq = (const float*)d_in[1];
    const float* bq = (const float*)d_in[2];
    const float* Wk = (const float*)d_in[3];
    const float* bk = (const float*)d_in[4];
    const float* Wv = (const float*)d_in[5];
    const float* bv = (const float*)d_in[6];
    const float* Wo = (const float*)d_in[7];
    const float* bo = (const float*)d_in[8];
    float* out = (float*)d_out;

    float *qp, *kp, *vp, *yp;
    cudaGetSymbolAddress((void**)&qp, g_Q);
    cudaGetSymbolAddress((void**)&kp, g_K);
    cudaGetSymbolAddress((void**)&vp, g_V);
    cudaGetSymbolAddress((void**)&yp, g_Y);

    dim3 gg(DM/64, MTOT/64);   // (16, 128)
    gemm_bias<0><<<gg, 256>>>(x, Wq, bq, qp);
    gemm_bias<0><<<gg, 256>>>(x, Wk, bk, kp);
    gemm_bias<0><<<gg, 256>>>(x, Wv, bv, vp);

    size_t smem = SMEM_FLOATS * sizeof(float);   // ~67 KB
    cudaFuncSetAttribute(attn_kernel,
                         cudaFuncAttributeMaxDynamicSharedMemorySize, (int)smem);
    attn_kernel<<<dim3(SEQ/64, BATCH*NH), 256, smem>>>(qp, kp, vp, yp);

    gemm_bias<1><<<gg, 256>>>(yp, Wo, bo, out);
}

// round 3
// speedup vs baseline: 2.3272x; 2.3257x over previous
#include <cuda_runtime.h>
#include <math_constants.h>
#include <cstdint>

#define BATCH 4
#define SEQ   2048
#define DM    1024
#define NH    16
#define HD    64
#define MTOT  (BATCH*SEQ)   // 8192

// Scratch (device globals: allocation-free rule)
__device__ float g_Q[BATCH*NH*SEQ*HD];  // [b,h,s,hd]
__device__ float g_K[BATCH*NH*SEQ*HD];
__device__ float g_V[BATCH*NH*SEQ*HD];
__device__ float g_Y[MTOT*DM];          // [b,s,D]

// ---------------------------------------------------------------------------
// tf32 helpers
// ---------------------------------------------------------------------------
__device__ __forceinline__ uint32_t f2tf(float f) {
    uint32_t u;
    asm("cvt.rna.tf32.f32 %0, %1;" : "=r"(u) : "f"(f));
    return u;
}

__device__ __forceinline__ void mma8(float4& d, const uint32_t a[4], const uint32_t b[2]) {
    asm volatile(
        "mma.sync.aligned.m16n8k8.row.col.f32.tf32.tf32.f32 "
        "{%0,%1,%2,%3}, {%4,%5,%6,%7}, {%8,%9}, {%0,%1,%2,%3};"
        : "+f"(d.x), "+f"(d.y), "+f"(d.z), "+f"(d.w)
        : "r"(a[0]), "r"(a[1]), "r"(a[2]), "r"(a[3]), "r"(b[0]), "r"(b[1]));
}

// ---------------------------------------------------------------------------
// GEMM + bias via tf32 mma: C = A[M,1024] @ W[1024,1024] + bias
// MODE 0: head-split output [b,h,s,hd]; MODE 1: row-major [m,n]
// 128x128 tile, BK=16, 256 threads (8 warps, 2x4), warp tile 64x32.
// ---------------------------------------------------------------------------
#define GS 136   // smem row stride (136%32==8 -> conflict-free frag loads)

template<int MODE>
__global__ __launch_bounds__(256)
void gemm_tc(const float* __restrict__ A,
             const float* __restrict__ W,
             const float* __restrict__ bias,
             float* __restrict__ C) {
    __shared__ uint32_t As[16][GS];   // [k][m]
    __shared__ uint32_t Bs[16][GS];   // [k][n]

    const int tid  = threadIdx.x;
    const int lane = tid & 31;
    const int warp = tid >> 5;
    const int g = lane >> 2, t = lane & 3;
    const int wm = (warp >> 2) * 64;    // 0 / 64
    const int wn = (warp & 3)  * 32;    // 0..96
    const int bm = blockIdx.y * 128;
    const int bn = blockIdx.x * 128;

    // gmem load assignments
    const int am  = tid & 63;           // A row (and +64)
    const int akg = (tid >> 6) * 4;     // A k group 0,4,8,12
    const int br  = tid >> 5;           // B k row (and +8)
    const int bc  = (lane) * 4;         // B col group

    const float* Ap = A + (size_t)(bm + am) * DM + akg;
    const float* Wp = W + (size_t)br * DM + bn + bc;

    float4 acc[4][4];
    #pragma unroll
    for (int i = 0; i < 4; i++)
        #pragma unroll
        for (int j = 0; j < 4; j++) acc[i][j] = make_float4(0.f,0.f,0.f,0.f);

    float4 pa0 = *(const float4*)(Ap);
    float4 pa1 = *(const float4*)(Ap + (size_t)64 * DM);
    float4 pb0 = *(const float4*)(Wp);
    float4 pb1 = *(const float4*)(Wp + (size_t)8 * DM);

    const int NITER = DM / 16;
    for (int kt = 0; kt < NITER; kt++) {
        // store current tile (with rna conversion to tf32)
        As[akg+0][am] = f2tf(pa0.x); As[akg+1][am] = f2tf(pa0.y);
        As[akg+2][am] = f2tf(pa0.z); As[akg+3][am] = f2tf(pa0.w);
        As[akg+0][am+64] = f2tf(pa1.x); As[akg+1][am+64] = f2tf(pa1.y);
        As[akg+2][am+64] = f2tf(pa1.z); As[akg+3][am+64] = f2tf(pa1.w);
        {
            uint4 u0 = make_uint4(f2tf(pb0.x), f2tf(pb0.y), f2tf(pb0.z), f2tf(pb0.w));
            uint4 u1 = make_uint4(f2tf(pb1.x), f2tf(pb1.y), f2tf(pb1.z), f2tf(pb1.w));
            *(uint4*)&Bs[br][bc]   = u0;
            *(uint4*)&Bs[br+8][bc] = u1;
        }
        __syncthreads();

        if (kt + 1 < NITER) {
            const float* Ap2 = Ap + (kt+1)*16;
            pa0 = *(const float4*)(Ap2);
            pa1 = *(const float4*)(Ap2 + (size_t)64 * DM);
            const float* Wp2 = Wp + (size_t)(kt+1) * 16 * DM;
            pb0 = *(const float4*)(Wp2);
            pb1 = *(const float4*)(Wp2 + (size_t)8 * DM);
        }

        #pragma unroll
        for (int ks = 0; ks < 2; ks++) {
            uint32_t bf[4][2];
            #pragma unroll
            for (int nt = 0; nt < 4; nt++) {
                int n = wn + nt*8 + g;
                bf[nt][0] = Bs[ks*8 + t][n];
                bf[nt][1] = Bs[ks*8 + t + 4][n];
            }
            #pragma unroll
            for (int mt = 0; mt < 4; mt++) {
                uint32_t af[4];
                int m = wm + mt*16 + g;
                af[0] = As[ks*8 + t][m];
                af[1] = As[ks*8 + t][m + 8];
                af[2] = As[ks*8 + t + 4][m];
                af[3] = As[ks*8 + t + 4][m + 8];
                #pragma unroll
                for (int nt = 0; nt < 4; nt++) mma8(acc[mt][nt], af, bf[nt]);
            }
        }
        __syncthreads();
    }

    // epilogue: bias + store
    #pragma unroll
    for (int mt = 0; mt < 4; mt++) {
        int m0 = bm + wm + mt*16 + g;
        #pragma unroll
        for (int nt = 0; nt < 4; nt++) {
            int n = bn + wn + nt*8 + 2*t;
            float2 bb = *(const float2*)(bias + n);
            float2 r0 = make_float2(acc[mt][nt].x + bb.x, acc[mt][nt].y + bb.y);
            float2 r1 = make_float2(acc[mt][nt].z + bb.x, acc[mt][nt].w + bb.y);
            if (MODE == 0) {
                int h = n >> 6, dd = n & 63;
                int b0i = m0 >> 11, s0 = m0 & (SEQ-1);
                *(float2*)&C[(((size_t)(b0i*NH + h))*SEQ + s0)*HD + dd] = r0;
                int m1 = m0 + 8;
                int b1i = m1 >> 11, s1 = m1 & (SEQ-1);
                *(float2*)&C[(((size_t)(b1i*NH + h))*SEQ + s1)*HD + dd] = r1;
            } else {
                *(float2*)&C[(size_t)m0*DM + n]     = r0;
                *(float2*)&C[(size_t)(m0+8)*DM + n] = r1;
            }
        }
    }
}

// ---------------------------------------------------------------------------
// Flash attention with tf32 mma.
// Per CTA: 128 q-rows of one (b,h). 8 warps x 16 q-rows. Key tiles of 64.
// smem: P/Q-stage [128][72], K [64][72], V [64][72]  (uint32 tf32)
// ---------------------------------------------------------------------------
#define AS 72
#define SM_K (128*AS)
#define SM_V (128*AS + 64*AS)
#define ATT_SMEM ((128+64+64)*AS*4)

__global__ __launch_bounds__(256)
void attn_tc(const float* __restrict__ Q, const float* __restrict__ K,
             const float* __restrict__ V, float* __restrict__ Y) {
    extern __shared__ uint32_t sm[];
    uint32_t* Ps = sm;            // Q staging, then P tiles
    uint32_t* Ks = sm + SM_K;
    uint32_t* Vs = sm + SM_V;

    const int tid  = threadIdx.x;
    const int lane = tid & 31;
    const int warp = tid >> 5;
    const int g = lane >> 2, t = lane & 3;
    const int wq = warp * 16;
    const int qb = blockIdx.x * 128;
    const int bh = blockIdx.y;

    const float* Qp = Q + ((size_t)bh * SEQ + qb) * HD;
    const float* Kp = K + (size_t)bh * SEQ * HD;
    const float* Vp = V + (size_t)bh * SEQ * HD;

    // stage Q (pre-scaled by 1/sqrt(64)) into Ps
    #pragma unroll
    for (int i = 0; i < 8; i++) {
        int idx = i*256 + tid;
        int r = idx >> 4, c = (idx & 15) * 4;
        float4 v = *(const float4*)(Qp + (size_t)r*HD + c);
        uint4 u = make_uint4(f2tf(v.x*0.125f), f2tf(v.y*0.125f),
                             f2tf(v.z*0.125f), f2tf(v.w*0.125f));
        *(uint4*)&Ps[r*AS + c] = u;
    }
    __syncthreads();

    // cache Q fragments in registers for all key tiles
    uint32_t qf[8][4];
    #pragma unroll
    for (int ks = 0; ks < 8; ks++) {
        int base = (wq + g)*AS + ks*8 + t;
        qf[ks][0] = Ps[base];
        qf[ks][1] = Ps[base + 8*AS];
        qf[ks][2] = Ps[base + 4];
        qf[ks][3] = Ps[base + 8*AS + 4];
    }

    float4 of[8];
    #pragma unroll
    for (int nt = 0; nt < 8; nt++) of[nt] = make_float4(0.f,0.f,0.f,0.f);
    float m0 = -CUDART_INF_F, m1 = -CUDART_INF_F, l0 = 0.f, l1 = 0.f;

    for (int kb = 0; kb < SEQ; kb += 64) {
        __syncthreads();   // previous tile fully consumed (also orders P vs qf loads)
        #pragma unroll
        for (int i = 0; i < 4; i++) {
            int idx = i*256 + tid;
            int r = idx >> 4, c = (idx & 15) * 4;
            float4 kv = *(const float4*)(Kp + (size_t)(kb + r)*HD + c);
            *(uint4*)&Ks[r*AS + c] = make_uint4(f2tf(kv.x), f2tf(kv.y), f2tf(kv.z), f2tf(kv.w));
            float4 vv = *(const float4*)(Vp + (size_t)(kb + r)*HD + c);
            *(uint4*)&Vs[r*AS + c] = make_uint4(f2tf(vv.x), f2tf(vv.y), f2tf(vv.z), f2tf(vv.w));
        }
        __syncthreads();

        // S = Qscaled @ K^T  (warp computes 16 x 64)
        float4 sa[8];
        #pragma unroll
        for (int nt = 0; nt < 8; nt++) sa[nt] = make_float4(0.f,0.f,0.f,0.f);
        #pragma unroll
        for (int ks = 0; ks < 8; ks++) {
            #pragma unroll
            for (int nt = 0; nt < 8; nt++) {
                uint32_t bf[2];
                int a = (nt*8 + g)*AS + ks*8 + t;
                bf[0] = Ks[a];
                bf[1] = Ks[a + 4];
                mma8(sa[nt], qf[ks], bf);
            }
        }

        // online softmax: thread owns rows (wq+g) [x,y] and (wq+g+8) [z,w]
        float mx0 = -CUDART_INF_F, mx1 = -CUDART_INF_F;
        #pragma unroll
        for (int nt = 0; nt < 8; nt++) {
            mx0 = fmaxf(mx0, fmaxf(sa[nt].x, sa[nt].y));
            mx1 = fmaxf(mx1, fmaxf(sa[nt].z, sa[nt].w));
        }
        mx0 = fmaxf(mx0, __shfl_xor_sync(0xffffffffu, mx0, 1));
        mx0 = fmaxf(mx0, __shfl_xor_sync(0xffffffffu, mx0, 2));
        mx1 = fmaxf(mx1, __shfl_xor_sync(0xffffffffu, mx1, 1));
        mx1 = fmaxf(mx1, __shfl_xor_sync(0xffffffffu, mx1, 2));
        float nm0 = fmaxf(m0, mx0), nm1 = fmaxf(m1, mx1);
        float al0 = __expf(m0 - nm0), al1 = __expf(m1 - nm1);
        float rs0 = 0.f, rs1 = 0.f;
        #pragma unroll
        for (int nt = 0; nt < 8; nt++) {
            float p00 = __expf(sa[nt].x - nm0);
            float p01 = __expf(sa[nt].y - nm0);
            float p10 = __expf(sa[nt].z - nm1);
            float p11 = __expf(sa[nt].w - nm1);
            rs0 += p00 + p01;
            rs1 += p10 + p11;
            int c = nt*8 + 2*t;
            *(uint2*)&Ps[(wq + g)*AS + c]     = make_uint2(f2tf(p00), f2tf(p01));
            *(uint2*)&Ps[(wq + g + 8)*AS + c] = make_uint2(f2tf(p10), f2tf(p11));
        }
        rs0 += __shfl_xor_sync(0xffffffffu, rs0, 1);
        rs0 += __shfl_xor_sync(0xffffffffu, rs0, 2);
        rs1 += __shfl_xor_sync(0xffffffffu, rs1, 1);
        rs1 += __shfl_xor_sync(0xffffffffu, rs1, 2);
        l0 = l0*al0 + rs0; m0 = nm0;
        l1 = l1*al1 + rs1; m1 = nm1;
        #pragma unroll
        for (int nt = 0; nt < 8; nt++) {
            of[nt].x *= al0; of[nt].y *= al0;
            of[nt].z *= al1; of[nt].w *= al1;
        }
        __syncwarp();   // P writes visible to own warp's frag loads

        // O += P @ V
        #pragma unroll
        for (int ks = 0; ks < 8; ks++) {
            uint32_t pf[4];
            int base = (wq + g)*AS + ks*8 + t;
            pf[0] = Ps[base];
            pf[1] = Ps[base + 8*AS];
            pf[2] = Ps[base + 4];
            pf[3] = Ps[base + 8*AS + 4];
            #pragma unroll
            for (int nt = 0; nt < 8; nt++) {
                uint32_t vf[2];
                int a = (ks*8 + t)*AS + nt*8 + g;
                vf[0] = Vs[a];
                vf[1] = Vs[a + 4*AS];
                mma8(of[nt], pf, vf);
            }
        }
    }

    // epilogue: normalize, write to Y [b,s,D]
    float inv0 = 1.f / l0, inv1 = 1.f / l1;
    int b = bh >> 4, h = bh & (NH-1);
    size_t row0 = (size_t)b * SEQ + qb + wq + g;
    #pragma unroll
    for (int nt = 0; nt < 8; nt++) {
        int dd = h*64 + nt*8 + 2*t;
        *(float2*)&Y[row0*DM + dd]       = make_float2(of[nt].x*inv0, of[nt].y*inv0);
        *(float2*)&Y[(row0 + 8)*DM + dd] = make_float2(of[nt].z*inv1, of[nt].w*inv1);
    }
}

// ---------------------------------------------------------------------------
extern "C" void kernel_launch(void* const* d_in, const int* in_sizes, int n_in,
                              void* d_out, int out_size) {
    const float* x  = (const float*)d_in[0];
    const float* Wq = (const float*)d_in[1];
    const float* bq = (const float*)d_in[2];
    const float* Wk = (const float*)d_in[3];
    const float* bk = (const float*)d_in[4];
    const float* Wv = (const float*)d_in[5];
    const float* bv = (const float*)d_in[6];
    const float* Wo = (const float*)d_in[7];
    const float* bo = (const float*)d_in[8];
    float* out = (float*)d_out;

    float *qp, *kp, *vp, *yp;
    cudaGetSymbolAddress((void**)&qp, g_Q);
    cudaGetSymbolAddress((void**)&kp, g_K);
    cudaGetSymbolAddress((void**)&vp, g_V);
    cudaGetSymbolAddress((void**)&yp, g_Y);

    dim3 gg(DM/128, MTOT/128);   // (8, 64)
    gemm_tc<0><<<gg, 256>>>(x, Wq, bq, qp);
    gemm_tc<0><<<gg, 256>>>(x, Wk, bk, kp);
    gemm_tc<0><<<gg, 256>>>(x, Wv, bv, vp);

    cudaFuncSetAttribute(attn_tc,
                         cudaFuncAttributeMaxDynamicSharedMemorySize, ATT_SMEM);
    attn_tc<<<dim3(SEQ/128, BATCH*NH), 256, ATT_SMEM>>>(qp, kp, vp, yp);

    gemm_tc<1><<<gg, 256>>>(yp, Wo, bo, out);
}

// round 4
// speedup vs baseline: 2.6443x; 1.1363x over previous
#include <cuda_runtime.h>
#include <math_constants.h>
#include <cstdint>

#define BATCH 4
#define SEQ   2048
#define DM    1024
#define NH    16
#define HD    64
#define MTOT  (BATCH*SEQ)   // 8192

// Scratch (device globals: allocation-free rule)
__device__ float g_Q[BATCH*NH*SEQ*HD];  // [b,h,s,hd]
__device__ float g_K[BATCH*NH*SEQ*HD];
__device__ float g_V[BATCH*NH*SEQ*HD];
__device__ float g_Y[MTOT*DM];          // [b,s,D]

// ---------------------------------------------------------------------------
// tf32 helpers
// ---------------------------------------------------------------------------
__device__ __forceinline__ uint32_t f2tf(float f) {
    uint32_t u;
    asm("cvt.rna.tf32.f32 %0, %1;" : "=r"(u) : "f"(f));
    return u;
}

__device__ __forceinline__ void mma8(float4& d, const uint32_t a[4], const uint32_t b[2]) {
    asm volatile(
        "mma.sync.aligned.m16n8k8.row.col.f32.tf32.tf32.f32 "
        "{%0,%1,%2,%3}, {%4,%5,%6,%7}, {%8,%9}, {%0,%1,%2,%3};"
        : "+f"(d.x), "+f"(d.y), "+f"(d.z), "+f"(d.w)
        : "r"(a[0]), "r"(a[1]), "r"(a[2]), "r"(a[3]), "r"(b[0]), "r"(b[1]));
}

// ---------------------------------------------------------------------------
// GEMM + bias via tf32 mma: C = A[M,1024] @ W[1024,1024] + bias
// 128x128 tile, BK=16, 2-stage smem double buffer, 1 sync/iter, 2 CTAs/SM.
// MODE 0: head-split output [b,h,s,hd]; MODE 1: row-major [m,n]
// ---------------------------------------------------------------------------
#define GS 136   // smem row stride (conflict-free frag loads: 8t'+g pattern)

template<int MODE>
__global__ __launch_bounds__(256, 2)
void gemm_tc(const float* __restrict__ A,
             const float* __restrict__ W,
             const float* __restrict__ bias,
             float* __restrict__ C) {
    __shared__ uint32_t As[2][16][GS];   // [stage][k][m]
    __shared__ uint32_t Bs[2][16][GS];   // [stage][k][n]

    const int tid  = threadIdx.x;
    const int lane = tid & 31;
    const int warp = tid >> 5;
    const int g = lane >> 2, t = lane & 3;
    const int wm = (warp >> 2) * 64;    // 0 / 64
    const int wn = (warp & 3)  * 32;    // 0..96
    const int bm = blockIdx.y * 128;
    const int bn = blockIdx.x * 128;

    const int am  = tid & 63;
    const int akg = (tid >> 6) * 4;
    const int br  = tid >> 5;
    const int bc  = lane * 4;

    const float* Ap = A + (size_t)(bm + am) * DM + akg;
    const float* Wp = W + (size_t)br * DM + bn + bc;

    float4 acc[4][4];
    #pragma unroll
    for (int i = 0; i < 4; i++)
        #pragma unroll
        for (int j = 0; j < 4; j++) acc[i][j] = make_float4(0.f,0.f,0.f,0.f);

    float4 pa0, pa1, pb0, pb1;

    #define G_LDG(kt) {                                                     \
        const float* A2 = Ap + (kt)*16;                                     \
        pa0 = *(const float4*)(A2);                                         \
        pa1 = *(const float4*)(A2 + (size_t)64 * DM);                       \
        const float* W2 = Wp + (size_t)(kt) * 16 * DM;                      \
        pb0 = *(const float4*)(W2);                                         \
        pb1 = *(const float4*)(W2 + (size_t)8 * DM); }

    #define G_STS(s) {                                                      \
        As[s][akg+0][am] = f2tf(pa0.x); As[s][akg+1][am] = f2tf(pa0.y);     \
        As[s][akg+2][am] = f2tf(pa0.z); As[s][akg+3][am] = f2tf(pa0.w);     \
        As[s][akg+0][am+64] = f2tf(pa1.x); As[s][akg+1][am+64] = f2tf(pa1.y);\
        As[s][akg+2][am+64] = f2tf(pa1.z); As[s][akg+3][am+64] = f2tf(pa1.w);\
        *(uint4*)&Bs[s][br][bc]   = make_uint4(f2tf(pb0.x), f2tf(pb0.y), f2tf(pb0.z), f2tf(pb0.w)); \
        *(uint4*)&Bs[s][br+8][bc] = make_uint4(f2tf(pb1.x), f2tf(pb1.y), f2tf(pb1.z), f2tf(pb1.w)); }

    const int NITER = DM / 16;    // 64
    G_LDG(0);
    G_STS(0);
    G_LDG(1);
    __syncthreads();

    for (int kt = 0; kt < NITER; kt++) {
        const int cur = kt & 1;
        if (kt + 1 < NITER) { G_STS((kt+1)&1); }
        if (kt + 2 < NITER) { G_LDG(kt+2); }

        #pragma unroll
        for (int ks = 0; ks < 2; ks++) {
            uint32_t bf[4][2];
            #pragma unroll
            for (int nt = 0; nt < 4; nt++) {
                int n = wn + nt*8 + g;
                bf[nt][0] = Bs[cur][ks*8 + t][n];
                bf[nt][1] = Bs[cur][ks*8 + t + 4][n];
            }
            #pragma unroll
            for (int mt = 0; mt < 4; mt++) {
                uint32_t af[4];
                int m = wm + mt*16 + g;
                af[0] = As[cur][ks*8 + t][m];
                af[1] = As[cur][ks*8 + t][m + 8];
                af[2] = As[cur][ks*8 + t + 4][m];
                af[3] = As[cur][ks*8 + t + 4][m + 8];
                #pragma unroll
                for (int nt = 0; nt < 4; nt++) mma8(acc[mt][nt], af, bf[nt]);
            }
        }
        __syncthreads();
    }
    #undef G_LDG
    #undef G_STS

    // epilogue: bias + store
    #pragma unroll
    for (int mt = 0; mt < 4; mt++) {
        int m0 = bm + wm + mt*16 + g;
        #pragma unroll
        for (int nt = 0; nt < 4; nt++) {
            int n = bn + wn + nt*8 + 2*t;
            float2 bb = *(const float2*)(bias + n);
            float2 r0 = make_float2(acc[mt][nt].x + bb.x, acc[mt][nt].y + bb.y);
            float2 r1 = make_float2(acc[mt][nt].z + bb.x, acc[mt][nt].w + bb.y);
            if (MODE == 0) {
                int h = n >> 6, dd = n & 63;
                int b0i = m0 >> 11, s0 = m0 & (SEQ-1);
                *(float2*)&C[(((size_t)(b0i*NH + h))*SEQ + s0)*HD + dd] = r0;
                int m1 = m0 + 8;
                int b1i = m1 >> 11, s1 = m1 & (SEQ-1);
                *(float2*)&C[(((size_t)(b1i*NH + h))*SEQ + s1)*HD + dd] = r1;
            } else {
                *(float2*)&C[(size_t)m0*DM + n]     = r0;
                *(float2*)&C[(size_t)(m0+8)*DM + n] = r1;
            }
        }
    }
}

// ---------------------------------------------------------------------------
// Flash attention, tf32 mma. 256 q-rows/CTA, 8 warps x 32 q-rows.
// K/V double-buffered (2 stages), 1 syncthreads per kv-tile.
// Layouts: Qs/Ps [256][68] natural (4g+t bank pattern, conflict-free)
//          Ks [key][hd^(4*(key&7))] stride 72 (XOR swizzle, conflict-free)
//          Vs [key][hd] stride 72 (8t+g pattern, conflict-free)
// ---------------------------------------------------------------------------
#define PQS   68
#define KVS   72
#define KVSZ  (64*KVS)
#define QW    (256*PQS)
#define ATT_SMEM ((2*QW + 4*KVSZ) * 4)   // 212992 bytes

__global__ __launch_bounds__(256)
void attn_tc(const float* __restrict__ Q, const float* __restrict__ K,
             const float* __restrict__ V, float* __restrict__ Y) {
    extern __shared__ uint32_t sm[];
    uint32_t* Qs = sm;                 // [256][68]
    uint32_t* Ps = sm + QW;            // [256][68]
    uint32_t* Ks = sm + 2*QW;          // 2 stages x [64][72]
    uint32_t* Vs = Ks + 2*KVSZ;        // 2 stages x [64][72]

    const int tid  = threadIdx.x;
    const int lane = tid & 31;
    const int warp = tid >> 5;
    const int g = lane >> 2, t = lane & 3;
    const int wq = warp * 32;
    const int qb = blockIdx.x * 256;
    const int bh = blockIdx.y;

    const float* Qp = Q + ((size_t)bh * SEQ + qb) * HD;
    const float* Kp = K + (size_t)bh * SEQ * HD;
    const float* Vp = V + (size_t)bh * SEQ * HD;

    // stage Q (pre-scaled by 1/sqrt(64)=0.125) into Qs
    #pragma unroll
    for (int i = 0; i < 16; i++) {
        int idx = i*256 + tid;
        int r = idx >> 4, c = (idx & 15) * 4;
        float4 v = *(const float4*)(Qp + (size_t)r*HD + c);
        *(uint4*)&Qs[r*PQS + c] = make_uint4(f2tf(v.x*0.125f), f2tf(v.y*0.125f),
                                             f2tf(v.z*0.125f), f2tf(v.w*0.125f));
    }

    float4 kr[4], vr[4];
    #define A_LDG(kbi) {                                                    \
        const float* kp = Kp + (size_t)(kbi)*64*HD;                         \
        const float* vp = Vp + (size_t)(kbi)*64*HD;                         \
        _Pragma("unroll")                                                   \
        for (int it = 0; it < 4; it++) {                                    \
            int fl = it*256 + tid;                                          \
            int r = fl >> 4, c = (fl & 15) * 4;                             \
            kr[it] = *(const float4*)(kp + (size_t)r*HD + c);               \
            vr[it] = *(const float4*)(vp + (size_t)r*HD + c);               \
        } }

    #define A_STS(s) {                                                      \
        uint32_t* Kd = Ks + (s)*KVSZ;                                       \
        uint32_t* Vd = Vs + (s)*KVSZ;                                       \
        _Pragma("unroll")                                                   \
        for (int it = 0; it < 4; it++) {                                    \
            int fl = it*256 + tid;                                          \
            int r = fl >> 4, c = (fl & 15) * 4;                             \
            int kc = c ^ ((r & 7) << 2);                                    \
            *(uint4*)&Kd[r*KVS + kc] = make_uint4(f2tf(kr[it].x), f2tf(kr[it].y), f2tf(kr[it].z), f2tf(kr[it].w)); \
            *(uint4*)&Vd[r*KVS + c]  = make_uint4(f2tf(vr[it].x), f2tf(vr[it].y), f2tf(vr[it].z), f2tf(vr[it].w)); \
        } }

    float4 of[2][8];
    #pragma unroll
    for (int mt = 0; mt < 2; mt++)
        #pragma unroll
        for (int nt = 0; nt < 8; nt++) of[mt][nt] = make_float4(0.f,0.f,0.f,0.f);
    float m_[2][2], l_[2][2];
    #pragma unroll
    for (int mt = 0; mt < 2; mt++) {
        m_[mt][0] = -CUDART_INF_F; m_[mt][1] = -CUDART_INF_F;
        l_[mt][0] = 0.f;           l_[mt][1] = 0.f;
    }

    const int NT = SEQ / 64;   // 32
    A_LDG(0);
    A_STS(0);
    A_LDG(1);
    __syncthreads();

    for (int kbi = 0; kbi < NT; kbi++) {
        const int cur = kbi & 1;
        if (kbi + 1 < NT) { A_STS((kbi+1)&1); }
        if (kbi + 2 < NT) { A_LDG(kbi+2); }

        const uint32_t* Kst = Ks + cur*KVSZ;
        const uint32_t* Vst = Vs + cur*KVSZ;

        // ---- S = Qscaled @ K^T : per warp 32x64 ----
        float4 sa[2][8];
        #pragma unroll
        for (int mt = 0; mt < 2; mt++)
            #pragma unroll
            for (int nt = 0; nt < 8; nt++) sa[mt][nt] = make_float4(0.f,0.f,0.f,0.f);

        #pragma unroll
        for (int ks = 0; ks < 8; ks++) {
            uint32_t qf[2][4];
            #pragma unroll
            for (int mt = 0; mt < 2; mt++) {
                int base = (wq + mt*16 + g)*PQS + ks*8 + t;
                qf[mt][0] = Qs[base];
                qf[mt][1] = Qs[base + 8*PQS];
                qf[mt][2] = Qs[base + 4];
                qf[mt][3] = Qs[base + 8*PQS + 4];
            }
            #pragma unroll
            for (int nt = 0; nt < 8; nt++) {
                uint32_t kf[2];
                int rowb = (nt*8 + g)*KVS;
                int sw = g << 2;
                kf[0] = Kst[rowb + ((ks*8 + t) ^ sw)];
                kf[1] = Kst[rowb + ((ks*8 + t + 4) ^ sw)];
                mma8(sa[0][nt], qf[0], kf);
                mma8(sa[1][nt], qf[1], kf);
            }
        }

        // ---- online softmax + P store ----
        #pragma unroll
        for (int mt = 0; mt < 2; mt++) {
            float mx0 = -CUDART_INF_F, mx1 = -CUDART_INF_F;
            #pragma unroll
            for (int nt = 0; nt < 8; nt++) {
                mx0 = fmaxf(mx0, fmaxf(sa[mt][nt].x, sa[mt][nt].y));
                mx1 = fmaxf(mx1, fmaxf(sa[mt][nt].z, sa[mt][nt].w));
            }
            mx0 = fmaxf(mx0, __shfl_xor_sync(0xffffffffu, mx0, 1));
            mx0 = fmaxf(mx0, __shfl_xor_sync(0xffffffffu, mx0, 2));
            mx1 = fmaxf(mx1, __shfl_xor_sync(0xffffffffu, mx1, 1));
            mx1 = fmaxf(mx1, __shfl_xor_sync(0xffffffffu, mx1, 2));
            float nm0 = fmaxf(m_[mt][0], mx0), nm1 = fmaxf(m_[mt][1], mx1);
            float al0 = __expf(m_[mt][0] - nm0), al1 = __expf(m_[mt][1] - nm1);
            float rs0 = 0.f, rs1 = 0.f;
            int r0 = (wq + mt*16 + g)*PQS;
            int r1 = r0 + 8*PQS;
            #pragma unroll
            for (int nt = 0; nt < 8; nt++) {
                float p00 = __expf(sa[mt][nt].x - nm0);
                float p01 = __expf(sa[mt][nt].y - nm0);
                float p10 = __expf(sa[mt][nt].z - nm1);
                float p11 = __expf(sa[mt][nt].w - nm1);
                rs0 += p00 + p01;
                rs1 += p10 + p11;
                int c = nt*8 + 2*t;
                *(uint2*)&Ps[r0 + c] = make_uint2(f2tf(p00), f2tf(p01));
                *(uint2*)&Ps[r1 + c] = make_uint2(f2tf(p10), f2tf(p11));
            }
            rs0 += __shfl_xor_sync(0xffffffffu, rs0, 1);
            rs0 += __shfl_xor_sync(0xffffffffu, rs0, 2);
            rs1 += __shfl_xor_sync(0xffffffffu, rs1, 1);
            rs1 += __shfl_xor_sync(0xffffffffu, rs1, 2);
            l_[mt][0] = l_[mt][0]*al0 + rs0; m_[mt][0] = nm0;
            l_[mt][1] = l_[mt][1]*al1 + rs1; m_[mt][1] = nm1;
            #pragma unroll
            for (int nt = 0; nt < 8; nt++) {
                of[mt][nt].x *= al0; of[mt][nt].y *= al0;
                of[mt][nt].z *= al1; of[mt][nt].w *= al1;
            }
        }
        __syncwarp();   // P writes -> own warp's frag loads

        // ---- O += P @ V ----
        #pragma unroll
        for (int ks = 0; ks < 8; ks++) {
            uint32_t pf[2][4];
            #pragma unroll
            for (int mt = 0; mt < 2; mt++) {
                int base = (wq + mt*16 + g)*PQS + ks*8 + t;
                pf[mt][0] = Ps[base];
                pf[mt][1] = Ps[base + 8*PQS];
                pf[mt][2] = Ps[base + 4];
                pf[mt][3] = Ps[base + 8*PQS + 4];
            }
            #pragma unroll
            for (int nt = 0; nt < 8; nt++) {
                uint32_t vf[2];
                int a = (ks*8 + t)*KVS + nt*8 + g;
                vf[0] = Vst[a];
                vf[1] = Vst[a + 4*KVS];
                mma8(of[0][nt], pf[0], vf);
                mma8(of[1][nt], pf[1], vf);
            }
        }
        __syncthreads();
    }
    #undef A_LDG
    #undef A_STS

    // epilogue: normalize, write Y [b,s,D]
    int b = bh >> 4, h = bh & (NH-1);
    #pragma unroll
    for (int mt = 0; mt < 2; mt++) {
        float inv0 = 1.f / l_[mt][0], inv1 = 1.f / l_[mt][1];
        size_t row0 = (size_t)b * SEQ + qb + wq + mt*16 + g;
        #pragma unroll
        for (int nt = 0; nt < 8; nt++) {
            int dd = h*64 + nt*8 + 2*t;
            *(float2*)&Y[row0*DM + dd]       = make_float2(of[mt][nt].x*inv0, of[mt][nt].y*inv0);
            *(float2*)&Y[(row0 + 8)*DM + dd] = make_float2(of[mt][nt].z*inv1, of[mt][nt].w*inv1);
        }
    }
}

// ---------------------------------------------------------------------------
extern "C" void kernel_launch(void* const* d_in, const int* in_sizes, int n_in,
                              void* d_out, int out_size) {
    const float* x  = (const float*)d_in[0];
    const float* Wq = (const float*)d_in[1];
    const float* bq = (const float*)d_in[2];
    const float* Wk = (const float*)d_in[3];
    const float* bk = (const float*)d_in[4];
    const float* Wv = (const float*)d_in[5];
    const float* bv = (const float*)d_in[6];
    const float* Wo = (const float*)d_in[7];
    const float* bo = (const float*)d_in[8];
    float* out = (float*)d_out;

    float *qp, *kp, *vp, *yp;
    cudaGetSymbolAddress((void**)&qp, g_Q);
    cudaGetSymbolAddress((void**)&kp, g_K);
    cudaGetSymbolAddress((void**)&vp, g_V);
    cudaGetSymbolAddress((void**)&yp, g_Y);

    dim3 gg(DM/128, MTOT/128);   // (8, 64)
    gemm_tc<0><<<gg, 256>>>(x, Wq, bq, qp);
    gemm_tc<0><<<gg, 256>>>(x, Wk, bk, kp);
    gemm_tc<0><<<gg, 256>>>(x, Wv, bv, vp);

    cudaFuncSetAttribute(attn_tc,
                         cudaFuncAttributeMaxDynamicSharedMemorySize, ATT_SMEM);
    attn_tc<<<dim3(SEQ/256, BATCH*NH), 256, ATT_SMEM>>>(qp, kp, vp, yp);

    gemm_tc<1><<<gg, 256>>>(yp, Wo, bo, out);
}

// round 5
// speedup vs baseline: 3.0209x; 1.1424x over previous
#include <cuda_runtime.h>
#include <math_constants.h>
#include <cstdint>

#define BATCH 4
#define SEQ   2048
#define DM    1024
#define NH    16
#define HD    64
#define MTOT  (BATCH*SEQ)   // 8192

// Scratch (device globals: allocation-free rule). All tf32 bit patterns.
__device__ uint32_t g_xt[MTOT*DM];        // x converted to tf32
__device__ uint32_t g_Wt[4][DM*DM];       // Wq,Wk,Wv,Wo converted to tf32
__device__ uint32_t g_Q[BATCH*NH*SEQ*HD]; // [b,h,s,hd] tf32 (pre-scaled 0.125)
__device__ uint32_t g_K[BATCH*NH*SEQ*HD];
__device__ uint32_t g_V[BATCH*NH*SEQ*HD];
__device__ uint32_t g_Y[MTOT*DM];         // [b,s,D] attn out, tf32

// ---------------------------------------------------------------------------
// helpers
// ---------------------------------------------------------------------------
__device__ __forceinline__ uint32_t f2tf(float f) {
    uint32_t u;
    asm("cvt.rna.tf32.f32 %0, %1;" : "=r"(u) : "f"(f));
    return u;
}
__device__ __forceinline__ void mma8(float4& d, const uint32_t a[4], const uint32_t b[2]) {
    asm volatile(
        "mma.sync.aligned.m16n8k8.row.col.f32.tf32.tf32.f32 "
        "{%0,%1,%2,%3}, {%4,%5,%6,%7}, {%8,%9}, {%0,%1,%2,%3};"
        : "+f"(d.x), "+f"(d.y), "+f"(d.z), "+f"(d.w)
        : "r"(a[0]), "r"(a[1]), "r"(a[2]), "r"(a[3]), "r"(b[0]), "r"(b[1]));
}
__device__ __forceinline__ void cpa16(uint32_t dst, const void* src) {
    asm volatile("cp.async.cg.shared.global [%0], [%1], 16;" :: "r"(dst), "l"(src) : "memory");
}
__device__ __forceinline__ void cp_commit() {
    asm volatile("cp.async.commit_group;" ::: "memory");
}
template<int N>
__device__ __forceinline__ void cp_wait() {
    asm volatile("cp.async.wait_group %0;" :: "n"(N) : "memory");
}

// ---------------------------------------------------------------------------
// Elementwise tf32 conversion (rna)
// ---------------------------------------------------------------------------
__global__ void conv_tf32(const float4* __restrict__ in, uint4* __restrict__ out, int n4) {
    int i = blockIdx.x * blockDim.x + threadIdx.x;
    if (i < n4) {
        float4 v = in[i];
        out[i] = make_uint4(f2tf(v.x), f2tf(v.y), f2tf(v.z), f2tf(v.w));
    }
}

// ---------------------------------------------------------------------------
// GEMM + bias, tf32 inputs in gmem, 4-stage cp.async pipeline.
// C = A[M,1024] @ W[1024,1024] + bias; 128x128 tile, BK=16.
// MODE 0: writes tf32 bits head-split [b,h,s,hd], scaled; MODE 1: fp32 [m,n].
// ---------------------------------------------------------------------------
#define AS_G   20                 // A smem row stride ((20g+t)%32 distinct)
#define BS_G   136                // B smem row stride (+ row-parity XOR swizzle)
#define A_STG  (128*AS_G)         // 2560 u32
#define B_STG  (16*BS_G)          // 2176 u32
#define G_SMEM (4*(A_STG + B_STG)*4)   // 75776 bytes

template<int MODE>
__global__ __launch_bounds__(256, 2)
void gemm_tc(const uint32_t* __restrict__ A,
             const uint32_t* __restrict__ W,
             const float* __restrict__ bias,
             void* __restrict__ Cout, float scale) {
    extern __shared__ uint32_t sm[];
    uint32_t* smA = sm;                    // 4 stages x [128][20]
    uint32_t* smB = sm + 4*A_STG;          // 4 stages x [16][136]
    const uint32_t smA_u = (uint32_t)__cvta_generic_to_shared(smA);
    const uint32_t smB_u = (uint32_t)__cvta_generic_to_shared(smB);

    const int tid  = threadIdx.x;
    const int lane = tid & 31;
    const int warp = tid >> 5;
    const int g = lane >> 2, t = lane & 3;
    const int wm = (warp >> 2) * 64;
    const int wn = (warp & 3)  * 32;
    const int bm = blockIdx.y * 128;
    const int bn = blockIdx.x * 128;

    // cp.async assignments: A: 2 chunks (row a_m, k halves), B: 2 chunks
    const int a_m  = tid & 127;
    const int a_k0 = (tid >> 7) * 8;       // 0 or 8; chunks at a_k0, a_k0+4
    const int b_r  = tid >> 4;             // 0..15
    const int b_c  = (tid & 15) * 8;       // chunks at b_c, b_c+4
    const int b_sw = (b_r & 1) << 2;

    const uint32_t* Abase = A + (size_t)(bm + a_m) * DM + a_k0;
    const uint32_t* Wbase = W + (size_t)b_r * DM + bn + b_c;

    #define G_ISSUE(kt) {                                                     \
        uint32_t da = smA_u + (((kt)&3)*A_STG + a_m*AS_G + a_k0)*4;           \
        const uint32_t* sa_ = Abase + (kt)*16;                                \
        cpa16(da, sa_); cpa16(da + 16, sa_ + 4);                              \
        uint32_t db = smB_u + (((kt)&3)*B_STG + b_r*BS_G)*4;                  \
        const uint32_t* sb_ = Wbase + (size_t)(kt)*16*DM;                     \
        cpa16(db + (uint32_t)(b_c ^ b_sw)*4, sb_);                            \
        cpa16(db + (uint32_t)((b_c+4) ^ b_sw)*4, sb_ + 4);                    \
        cp_commit(); }

    float4 acc[4][4];
    #pragma unroll
    for (int i = 0; i < 4; i++)
        #pragma unroll
        for (int j = 0; j < 4; j++) acc[i][j] = make_float4(0.f,0.f,0.f,0.f);

    const int NITER = DM / 16;   // 64
    G_ISSUE(0); G_ISSUE(1); G_ISSUE(2);

    for (int kt = 0; kt < NITER; kt++) {
        if      (kt < NITER-2) cp_wait<2>();
        else if (kt == NITER-2) cp_wait<1>();
        else                    cp_wait<0>();
        __syncthreads();
        if (kt + 3 < NITER) { G_ISSUE(kt+3); }

        const uint32_t* As = smA + (kt&3)*A_STG;
        const uint32_t* Bs = smB + (kt&3)*B_STG;
        #pragma unroll
        for (int ks = 0; ks < 2; ks++) {
            uint32_t bf[4][2];
            const int kk = ks*8 + t;
            const int sw = (t & 1) << 2;
            #pragma unroll
            for (int nt = 0; nt < 4; nt++) {
                int col = (wn + nt*8 + g) ^ sw;
                bf[nt][0] = Bs[kk*BS_G + col];
                bf[nt][1] = Bs[(kk+4)*BS_G + col];
            }
            #pragma unroll
            for (int mt = 0; mt < 4; mt++) {
                uint32_t af[4];
                int base = (wm + mt*16 + g)*AS_G + kk;
                af[0] = As[base];
                af[1] = As[base + 8*AS_G];
                af[2] = As[base + 4];
                af[3] = As[base + 8*AS_G + 4];
                #pragma unroll
                for (int nt = 0; nt < 4; nt++) mma8(acc[mt][nt], af, bf[nt]);
            }
        }
        __syncthreads();
    }
    #undef G_ISSUE

    // epilogue
    #pragma unroll
    for (int mt = 0; mt < 4; mt++) {
        int m0 = bm + wm + mt*16 + g;
        #pragma unroll
        for (int nt = 0; nt < 4; nt++) {
            int n = bn + wn + nt*8 + 2*t;
            float2 bb = *(const float2*)(bias + n);
            float r0x = acc[mt][nt].x + bb.x, r0y = acc[mt][nt].y + bb.y;
            float r1x = acc[mt][nt].z + bb.x, r1y = acc[mt][nt].w + bb.y;
            if (MODE == 0) {
                uint32_t* C = (uint32_t*)Cout;
                int h = n >> 6, dd = n & 63;
                int b0i = m0 >> 11, s0 = m0 & (SEQ-1);
                *(uint2*)&C[(((size_t)(b0i*NH + h))*SEQ + s0)*HD + dd] =
                    make_uint2(f2tf(r0x*scale), f2tf(r0y*scale));
                int m1 = m0 + 8;
                int b1i = m1 >> 11, s1 = m1 & (SEQ-1);
                *(uint2*)&C[(((size_t)(b1i*NH + h))*SEQ + s1)*HD + dd] =
                    make_uint2(f2tf(r1x*scale), f2tf(r1y*scale));
            } else {
                float* C = (float*)Cout;
                *(float2*)&C[(size_t)m0*DM + n]     = make_float2(r0x, r0y);
                *(float2*)&C[(size_t)(m0+8)*DM + n] = make_float2(r1x, r1y);
            }
        }
    }
}

// ---------------------------------------------------------------------------
// Flash attention, tf32 mma, cp.async staging. 256 q-rows/CTA, 8 warps.
// Q pre-scaled tf32 in gmem. K/V tf32 in gmem, 2-stage cp.async.
// ---------------------------------------------------------------------------
#define PQS   68
#define KVS   72
#define KVSZ  (64*KVS)
#define QW    (256*PQS)
#define ATT_SMEM ((2*QW + 4*KVSZ) * 4)   // 212992 bytes

__global__ __launch_bounds__(256)
void attn_tc(const uint32_t* __restrict__ Q, const uint32_t* __restrict__ K,
             const uint32_t* __restrict__ V, uint32_t* __restrict__ Y) {
    extern __shared__ uint32_t sm[];
    uint32_t* Qs = sm;                 // [256][68]
    uint32_t* Ps = sm + QW;            // [256][68]
    uint32_t* Ks = sm + 2*QW;          // 2 x [64][72], XOR swizzled
    uint32_t* Vs = Ks + 2*KVSZ;        // 2 x [64][72]
    const uint32_t smQ_u = (uint32_t)__cvta_generic_to_shared(Qs);
    const uint32_t smK_u = (uint32_t)__cvta_generic_to_shared(Ks);
    const uint32_t smV_u = (uint32_t)__cvta_generic_to_shared(Vs);

    const int tid  = threadIdx.x;
    const int lane = tid & 31;
    const int warp = tid >> 5;
    const int g = lane >> 2, t = lane & 3;
    const int wq = warp * 32;
    const int qb = blockIdx.x * 256;
    const int bh = blockIdx.y;

    const uint32_t* Qp = Q + ((size_t)bh * SEQ + qb) * HD;
    const uint32_t* Kp = K + (size_t)bh * SEQ * HD;
    const uint32_t* Vp = V + (size_t)bh * SEQ * HD;

    #define AKV_ISSUE(kbi, slot) {                                            \
        const uint32_t* kp = Kp + (size_t)(kbi)*64*HD;                        \
        const uint32_t* vp = Vp + (size_t)(kbi)*64*HD;                        \
        uint32_t kb_ = smK_u + (slot)*KVSZ*4;                                 \
        uint32_t vb_ = smV_u + (slot)*KVSZ*4;                                 \
        _Pragma("unroll")                                                     \
        for (int it = 0; it < 4; it++) {                                      \
            int fl = it*256 + tid;                                            \
            int r = fl >> 4, c = (fl & 15) * 4;                               \
            int kc = c ^ ((r & 7) << 2);                                      \
            cpa16(kb_ + (uint32_t)(r*KVS + kc)*4, kp + (size_t)r*HD + c);     \
            cpa16(vb_ + (uint32_t)(r*KVS + c)*4,  vp + (size_t)r*HD + c);     \
        } }

    // prologue: Q + KV tile 0 (group), KV tile 1 (group)
    #pragma unroll
    for (int i = 0; i < 16; i++) {
        int idx = i*256 + tid;
        int r = idx >> 4, c = (idx & 15) * 4;
        cpa16(smQ_u + (uint32_t)(r*PQS + c)*4, Qp + (size_t)r*HD + c);
    }
    AKV_ISSUE(0, 0); cp_commit();
    AKV_ISSUE(1, 1); cp_commit();
    cp_wait<1>();
    __syncthreads();

    float4 of[2][8];
    #pragma unroll
    for (int mt = 0; mt < 2; mt++)
        #pragma unroll
        for (int nt = 0; nt < 8; nt++) of[mt][nt] = make_float4(0.f,0.f,0.f,0.f);
    float m_[2][2], l_[2][2];
    #pragma unroll
    for (int mt = 0; mt < 2; mt++) {
        m_[mt][0] = -CUDART_INF_F; m_[mt][1] = -CUDART_INF_F;
        l_[mt][0] = 0.f;           l_[mt][1] = 0.f;
    }

    const int NT = SEQ / 64;   // 32
    for (int kbi = 0; kbi < NT; kbi++) {
        const int cur = kbi & 1;
        const uint32_t* Kst = Ks + cur*KVSZ;
        const uint32_t* Vst = Vs + cur*KVSZ;

        // ---- S = Qscaled @ K^T ----
        float4 sa[2][8];
        #pragma unroll
        for (int mt = 0; mt < 2; mt++)
            #pragma unroll
            for (int nt = 0; nt < 8; nt++) sa[mt][nt] = make_float4(0.f,0.f,0.f,0.f);

        #pragma unroll
        for (int ks = 0; ks < 8; ks++) {
            uint32_t qf[2][4];
            #pragma unroll
            for (int mt = 0; mt < 2; mt++) {
                int base = (wq + mt*16 + g)*PQS + ks*8 + t;
                qf[mt][0] = Qs[base];
                qf[mt][1] = Qs[base + 8*PQS];
                qf[mt][2] = Qs[base + 4];
                qf[mt][3] = Qs[base + 8*PQS + 4];
            }
            #pragma unroll
            for (int nt = 0; nt < 8; nt++) {
                uint32_t kf[2];
                int rowb = (nt*8 + g)*KVS;
                int sw = g << 2;
                kf[0] = Kst[rowb + ((ks*8 + t) ^ sw)];
                kf[1] = Kst[rowb + ((ks*8 + t + 4) ^ sw)];
                mma8(sa[0][nt], qf[0], kf);
                mma8(sa[1][nt], qf[1], kf);
            }
        }

        // ---- online softmax + P store ----
        #pragma unroll
        for (int mt = 0; mt < 2; mt++) {
            float mx0 = -CUDART_INF_F, mx1 = -CUDART_INF_F;
            #pragma unroll
            for (int nt = 0; nt < 8; nt++) {
                mx0 = fmaxf(mx0, fmaxf(sa[mt][nt].x, sa[mt][nt].y));
                mx1 = fmaxf(mx1, fmaxf(sa[mt][nt].z, sa[mt][nt].w));
            }
            mx0 = fmaxf(mx0, __shfl_xor_sync(0xffffffffu, mx0, 1));
            mx0 = fmaxf(mx0, __shfl_xor_sync(0xffffffffu, mx0, 2));
            mx1 = fmaxf(mx1, __shfl_xor_sync(0xffffffffu, mx1, 1));
            mx1 = fmaxf(mx1, __shfl_xor_sync(0xffffffffu, mx1, 2));
            float nm0 = fmaxf(m_[mt][0], mx0), nm1 = fmaxf(m_[mt][1], mx1);
            float al0 = __expf(m_[mt][0] - nm0), al1 = __expf(m_[mt][1] - nm1);
            float rs0 = 0.f, rs1 = 0.f;
            int r0 = (wq + mt*16 + g)*PQS;
            int r1 = r0 + 8*PQS;
            #pragma unroll
            for (int nt = 0; nt < 8; nt++) {
                float p00 = __expf(sa[mt][nt].x - nm0);
                float p01 = __expf(sa[mt][nt].y - nm0);
                float p10 = __expf(sa[mt][nt].z - nm1);
                float p11 = __expf(sa[mt][nt].w - nm1);
                rs0 += p00 + p01;
                rs1 += p10 + p11;
                int c = nt*8 + 2*t;
                *(uint2*)&Ps[r0 + c] = make_uint2(f2tf(p00), f2tf(p01));
                *(uint2*)&Ps[r1 + c] = make_uint2(f2tf(p10), f2tf(p11));
            }
            rs0 += __shfl_xor_sync(0xffffffffu, rs0, 1);
            rs0 += __shfl_xor_sync(0xffffffffu, rs0, 2);
            rs1 += __shfl_xor_sync(0xffffffffu, rs1, 1);
            rs1 += __shfl_xor_sync(0xffffffffu, rs1, 2);
            l_[mt][0] = l_[mt][0]*al0 + rs0; m_[mt][0] = nm0;
            l_[mt][1] = l_[mt][1]*al1 + rs1; m_[mt][1] = nm1;
            #pragma unroll
            for (int nt = 0; nt < 8; nt++) {
                of[mt][nt].x *= al0; of[mt][nt].y *= al0;
                of[mt][nt].z *= al1; of[mt][nt].w *= al1;
            }
        }
        __syncwarp();   // P visible to own warp's frag loads

        // ---- O += P @ V ----
        #pragma unroll
        for (int ks = 0; ks < 8; ks++) {
            uint32_t pf[2][4];
            #pragma unroll
            for (int mt = 0; mt < 2; mt++) {
                int base = (wq + mt*16 + g)*PQS + ks*8 + t;
                pf[mt][0] = Ps[base];
                pf[mt][1] = Ps[base + 8*PQS];
                pf[mt][2] = Ps[base + 4];
                pf[mt][3] = Ps[base + 8*PQS + 4];
            }
            #pragma unroll
            for (int nt = 0; nt < 8; nt++) {
                uint32_t vf[2];
                int a = (ks*8 + t)*KVS + nt*8 + g;
                vf[0] = Vst[a];
                vf[1] = Vst[a + 4*KVS];
                mma8(of[0][nt], pf[0], vf);
                mma8(of[1][nt], pf[1], vf);
            }
        }

        __syncthreads();                 // done reading slot cur
        if (kbi + 2 < NT) {
            AKV_ISSUE(kbi+2, cur); cp_commit();
            cp_wait<1>();                // tile kbi+1 complete
        } else {
            cp_wait<0>();
        }
        __syncthreads();                 // next slot valid for all threads
    }
    #undef AKV_ISSUE

    // epilogue: normalize, convert to tf32, write Y [b,s,D]
    int b = bh >> 4, h = bh & (NH-1);
    #pragma unroll
    for (int mt = 0; mt < 2; mt++) {
        float inv0 = 1.f / l_[mt][0], inv1 = 1.f / l_[mt][1];
        size_t row0 = (size_t)b * SEQ + qb + wq + mt*16 + g;
        #pragma unroll
        for (int nt = 0; nt < 8; nt++) {
            int dd = h*64 + nt*8 + 2*t;
            *(uint2*)&Y[row0*DM + dd] =
                make_uint2(f2tf(of[mt][nt].x*inv0), f2tf(of[mt][nt].y*inv0));
            *(uint2*)&Y[(row0 + 8)*DM + dd] =
                make_uint2(f2tf(of[mt][nt].z*inv1), f2tf(of[mt][nt].w*inv1));
        }
    }
}

// ---------------------------------------------------------------------------
extern "C" void kernel_launch(void* const* d_in, const int* in_sizes, int n_in,
                              void* d_out, int out_size) {
    const float* x  = (const float*)d_in[0];
    const float* Wq = (const float*)d_in[1];
    const float* bq = (const float*)d_in[2];
    const float* Wk = (const float*)d_in[3];
    const float* bk = (const float*)d_in[4];
    const float* Wv = (const float*)d_in[5];
    const float* bv = (const float*)d_in[6];
    const float* Wo = (const float*)d_in[7];
    const float* bo = (const float*)d_in[8];
    float* out = (float*)d_out;

    uint32_t *xt, *wt, *qp, *kp, *vp, *yp;
    cudaGetSymbolAddress((void**)&xt, g_xt);
    cudaGetSymbolAddress((void**)&wt, g_Wt);
    cudaGetSymbolAddress((void**)&qp, g_Q);
    cudaGetSymbolAddress((void**)&kp, g_K);
    cudaGetSymbolAddress((void**)&vp, g_V);
    cudaGetSymbolAddress((void**)&yp, g_Y);
    uint32_t* wqt = wt;
    uint32_t* wkt = wt + (size_t)DM*DM;
    uint32_t* wvt = wt + (size_t)2*DM*DM;
    uint32_t* wot = wt + (size_t)3*DM*DM;

    // tf32 pre-conversion (rna)
    int nx4 = MTOT*DM/4, nw4 = DM*DM/4;
    conv_tf32<<<nx4/256, 256>>>((const float4*)x,  (uint4*)xt,  nx4);
    conv_tf32<<<nw4/256, 256>>>((const float4*)Wq, (uint4*)wqt, nw4);
    conv_tf32<<<nw4/256, 256>>>((const float4*)Wk, (uint4*)wkt, nw4);
    conv_tf32<<<nw4/256, 256>>>((const float4*)Wv, (uint4*)wvt, nw4);
    conv_tf32<<<nw4/256, 256>>>((const float4*)Wo, (uint4*)wot, nw4);

    cudaFuncSetAttribute(gemm_tc<0>, cudaFuncAttributeMaxDynamicSharedMemorySize, G_SMEM);
    cudaFuncSetAttribute(gemm_tc<1>, cudaFuncAttributeMaxDynamicSharedMemorySize, G_SMEM);
    cudaFuncSetAttribute(attn_tc,    cudaFuncAttributeMaxDynamicSharedMemorySize, ATT_SMEM);

    dim3 gg(DM/128, MTOT/128);   // (8, 64)
    gemm_tc<0><<<gg, 256, G_SMEM>>>(xt, wqt, bq, qp, 0.125f);  // Q pre-scaled
    gemm_tc<0><<<gg, 256, G_SMEM>>>(xt, wkt, bk, kp, 1.0f);
    gemm_tc<0><<<gg, 256, G_SMEM>>>(xt, wvt, bv, vp, 1.0f);

    attn_tc<<<dim3(SEQ/256, BATCH*NH), 256, ATT_SMEM>>>(qp, kp, vp, yp);

    gemm_tc<1><<<gg, 256, G_SMEM>>>(yp, wot, bo, out, 1.0f);
}